// round 5
// baseline (speedup 1.0000x reference)
#include <cuda_runtime.h>
#include <cuda_bf16.h>
#include <mma.h>

using namespace nvcuda;

#define Bn 8
#define Sn 8192
#define Cn 512
#define Hn 128

// Scratch (alloc-free rule: __device__ globals)
__device__ float g_logits[Bn * Sn * Hn];          // 32 MB
__device__ float g_ctxp[8][Bn * Hn * Cn];         // 16 MB split-K partials
__device__ float g_ctx[Bn * Hn * Cn];             // 2 MB
__device__ float g_zpart[Bn][64][Hn];             // per-K1-block partial Z
__device__ float g_invz[Bn * Hn];

#define SMEM_BYTES (128 * 132 * 4)

// ---------------------------------------------------------------------------
// K1: logits[b,s,h] = sum_c x[b,s,c] * W[c,h] + bias[h]
// Flattened GEMM [65536,512]@[512,128], TF32 wmma, 128x128 tile, BK=32,
// register-prefetch pipelined. Epilogue also emits partial Z = sum_s exp().
// ---------------------------------------------------------------------------
__global__ __launch_bounds__(256) void k1_logits(const float* __restrict__ x,
                                                 const float* __restrict__ W,
                                                 const float* __restrict__ bias) {
    extern __shared__ float sm[];
    float* As = sm;             // [128][36]
    float* Bs = sm + 128 * 36;  // [32][132]
    float* Cs = sm;             // [128][132] overlay (epilogue)
    __shared__ float red[256];

    const int m0 = blockIdx.x * 128;
    const int tid = threadIdx.x;
    const int warp = tid >> 5;
    const int wm = warp & 3, wn = warp >> 2;

    wmma::fragment<wmma::accumulator, 16, 16, 8, float> acc[2][4];
#pragma unroll
    for (int i = 0; i < 2; i++)
#pragma unroll
        for (int j = 0; j < 4; j++) wmma::fill_fragment(acc[i][j], 0.0f);

    // preload k0 = 0
#pragma unroll
    for (int u = 0; u < 4; u++) {
        int t = tid + 256 * u;
        int r = t >> 3, q = t & 7;
        *reinterpret_cast<float4*>(&As[r * 36 + q * 4]) =
            *reinterpret_cast<const float4*>(&x[(size_t)(m0 + r) * Cn + q * 4]);
    }
#pragma unroll
    for (int u = 0; u < 4; u++) {
        int t = tid + 256 * u;
        int r = t >> 5, q = t & 31;
        *reinterpret_cast<float4*>(&Bs[r * 132 + q * 4]) =
            *reinterpret_cast<const float4*>(&W[(size_t)r * Hn + q * 4]);
    }
    __syncthreads();

    const int NIT = Cn / 32;  // 16
    for (int it = 0; it < NIT; it++) {
        float4 pa[4], pb[4];
        if (it + 1 < NIT) {
            const int kn = (it + 1) * 32;
#pragma unroll
            for (int u = 0; u < 4; u++) {
                int t = tid + 256 * u;
                int r = t >> 3, q = t & 7;
                pa[u] = *reinterpret_cast<const float4*>(&x[(size_t)(m0 + r) * Cn + kn + q * 4]);
            }
#pragma unroll
            for (int u = 0; u < 4; u++) {
                int t = tid + 256 * u;
                int r = t >> 5, q = t & 31;
                pb[u] = *reinterpret_cast<const float4*>(&W[(size_t)(kn + r) * Hn + q * 4]);
            }
        }
#pragma unroll
        for (int kk = 0; kk < 32; kk += 8) {
            wmma::fragment<wmma::matrix_a, 16, 16, 8, wmma::precision::tf32, wmma::row_major> af[2];
            wmma::fragment<wmma::matrix_b, 16, 16, 8, wmma::precision::tf32, wmma::row_major> bf[4];
#pragma unroll
            for (int i = 0; i < 2; i++) {
                wmma::load_matrix_sync(af[i], &As[(wm * 32 + i * 16) * 36 + kk], 36);
#pragma unroll
                for (int e = 0; e < af[i].num_elements; e++)
                    af[i].x[e] = wmma::__float_to_tf32(af[i].x[e]);
            }
#pragma unroll
            for (int j = 0; j < 4; j++) {
                wmma::load_matrix_sync(bf[j], &Bs[kk * 132 + wn * 64 + j * 16], 132);
#pragma unroll
                for (int e = 0; e < bf[j].num_elements; e++)
                    bf[j].x[e] = wmma::__float_to_tf32(bf[j].x[e]);
            }
#pragma unroll
            for (int i = 0; i < 2; i++)
#pragma unroll
                for (int j = 0; j < 4; j++)
                    wmma::mma_sync(acc[i][j], af[i], bf[j], acc[i][j]);
        }
        __syncthreads();
        if (it + 1 < NIT) {
#pragma unroll
            for (int u = 0; u < 4; u++) {
                int t = tid + 256 * u;
                int r = t >> 3, q = t & 7;
                *reinterpret_cast<float4*>(&As[r * 36 + q * 4]) = pa[u];
            }
#pragma unroll
            for (int u = 0; u < 4; u++) {
                int t = tid + 256 * u;
                int r = t >> 5, q = t & 31;
                *reinterpret_cast<float4*>(&Bs[r * 132 + q * 4]) = pb[u];
            }
        }
        __syncthreads();
    }

#pragma unroll
    for (int i = 0; i < 2; i++)
#pragma unroll
        for (int j = 0; j < 4; j++)
            wmma::store_matrix_sync(&Cs[(wm * 32 + i * 16) * 132 + wn * 64 + j * 16],
                                    acc[i][j], 132, wmma::mem_row_major);
    __syncthreads();

    // write logits (+bias) and accumulate this block's partial Z from smem
#pragma unroll
    for (int t = tid; t < 4096; t += 256) {
        int r = t >> 5, q = t & 31;
        float4 v = *reinterpret_cast<float4*>(&Cs[r * 132 + q * 4]);
        float4 bb = *reinterpret_cast<const float4*>(&bias[q * 4]);
        v.x += bb.x; v.y += bb.y; v.z += bb.z; v.w += bb.w;
        *reinterpret_cast<float4*>(&g_logits[(size_t)(m0 + r) * Hn + q * 4]) = v;
    }

    const int h = tid & 127, half = tid >> 7;
    const float bh = bias[h];
    float zacc = 0.0f;
#pragma unroll
    for (int i = 0; i < 64; i++) {
        int r = 2 * i + half;
        zacc += __expf(Cs[r * 132 + h] + bh);
    }
    red[tid] = zacc;
    __syncthreads();
    if (tid < 128) {
        int bb = blockIdx.x >> 6;      // batch (64 m-tiles per batch)
        int mblk = blockIdx.x & 63;    // m-tile within batch
        g_zpart[bb][mblk][tid] = red[tid] + red[tid + 128];
    }
}

// K2b: invZ = 1 / sum over 64 block partials (deterministic fixed order)
__global__ void k2_invz() {
    int idx = blockIdx.x * 256 + threadIdx.x;  // 1024 total
    int b = idx >> 7, h = idx & 127;
    float z = 0.0f;
#pragma unroll
    for (int c = 0; c < 64; c++) z += g_zpart[b][c][h];
    g_invz[idx] = 1.0f / z;
}

// ---------------------------------------------------------------------------
// K3: ctx_partial[ks][b,h,c] = sum_{s in 1024-chunk} a[b,s,h] * x[b,s,c]
// A = a^T (col-major from logits, exp*invz applied during staging),
// split-K = 8 (deterministic partials), register-prefetch pipelined.
// ---------------------------------------------------------------------------
__global__ __launch_bounds__(256) void k3_ctx(const float* __restrict__ x) {
    extern __shared__ float sm[];
    float* As = sm;              // [32 s][132] (h contiguous)
    float* Bs = sm + 32 * 132;   // [32 s][132] (c contiguous)
    float* ivz = sm + 64 * 132;  // [128]
    float* Cs = sm;              // [128][132] overlay

    const int nt = blockIdx.x;   // c tile (0..3)
    const int ks = blockIdx.y;   // split-K chunk (0..7)
    const int b = blockIdx.z;
    const int tid = threadIdx.x;
    const int warp = tid >> 5;
    const int wm = warp & 3, wn = warp >> 2;

    if (tid < 128) ivz[tid] = g_invz[b * Hn + tid];
    __syncthreads();

    wmma::fragment<wmma::accumulator, 16, 16, 8, float> acc[2][4];
#pragma unroll
    for (int i = 0; i < 2; i++)
#pragma unroll
        for (int j = 0; j < 4; j++) wmma::fill_fragment(acc[i][j], 0.0f);

    const float* Lb = g_logits + (size_t)b * Sn * Hn;
    const float* Xb = x + (size_t)b * Sn * Cn + nt * 128;
    const int kbase = ks * 1024;

    // preload first s-tile
#pragma unroll
    for (int u = 0; u < 4; u++) {
        int t = tid + 256 * u;
        int r = t >> 5, q = t & 31;
        float4 v = *reinterpret_cast<const float4*>(&Lb[(size_t)(kbase + r) * Hn + q * 4]);
        int hh = q * 4;
        v.x = __expf(v.x) * ivz[hh + 0];
        v.y = __expf(v.y) * ivz[hh + 1];
        v.z = __expf(v.z) * ivz[hh + 2];
        v.w = __expf(v.w) * ivz[hh + 3];
        *reinterpret_cast<float4*>(&As[r * 132 + q * 4]) = v;
    }
#pragma unroll
    for (int u = 0; u < 4; u++) {
        int t = tid + 256 * u;
        int r = t >> 5, q = t & 31;
        *reinterpret_cast<float4*>(&Bs[r * 132 + q * 4]) =
            *reinterpret_cast<const float4*>(&Xb[(size_t)(kbase + r) * Cn + q * 4]);
    }
    __syncthreads();

    const int NIT = 32;  // 1024 / 32
    for (int it = 0; it < NIT; it++) {
        float4 pa[4], pb[4];
        if (it + 1 < NIT) {
            const int kn = kbase + (it + 1) * 32;
#pragma unroll
            for (int u = 0; u < 4; u++) {
                int t = tid + 256 * u;
                int r = t >> 5, q = t & 31;
                pa[u] = *reinterpret_cast<const float4*>(&Lb[(size_t)(kn + r) * Hn + q * 4]);
                pb[u] = *reinterpret_cast<const float4*>(&Xb[(size_t)(kn + r) * Cn + q * 4]);
            }
        }
#pragma unroll
        for (int kk = 0; kk < 32; kk += 8) {
            wmma::fragment<wmma::matrix_a, 16, 16, 8, wmma::precision::tf32, wmma::col_major> af[2];
            wmma::fragment<wmma::matrix_b, 16, 16, 8, wmma::precision::tf32, wmma::row_major> bf[4];
#pragma unroll
            for (int i = 0; i < 2; i++) {
                wmma::load_matrix_sync(af[i], &As[kk * 132 + wm * 32 + i * 16], 132);
#pragma unroll
                for (int e = 0; e < af[i].num_elements; e++)
                    af[i].x[e] = wmma::__float_to_tf32(af[i].x[e]);
            }
#pragma unroll
            for (int j = 0; j < 4; j++) {
                wmma::load_matrix_sync(bf[j], &Bs[kk * 132 + wn * 64 + j * 16], 132);
#pragma unroll
                for (int e = 0; e < bf[j].num_elements; e++)
                    bf[j].x[e] = wmma::__float_to_tf32(bf[j].x[e]);
            }
#pragma unroll
            for (int i = 0; i < 2; i++)
#pragma unroll
                for (int j = 0; j < 4; j++)
                    wmma::mma_sync(acc[i][j], af[i], bf[j], acc[i][j]);
        }
        __syncthreads();
        if (it + 1 < NIT) {
#pragma unroll
            for (int u = 0; u < 4; u++) {
                int t = tid + 256 * u;
                int r = t >> 5, q = t & 31;
                float4 v = pa[u];
                int hh = q * 4;
                v.x = __expf(v.x) * ivz[hh + 0];
                v.y = __expf(v.y) * ivz[hh + 1];
                v.z = __expf(v.z) * ivz[hh + 2];
                v.w = __expf(v.w) * ivz[hh + 3];
                *reinterpret_cast<float4*>(&As[r * 132 + q * 4]) = v;
                *reinterpret_cast<float4*>(&Bs[r * 132 + q * 4]) = pb[u];
            }
        }
        __syncthreads();
    }

#pragma unroll
    for (int i = 0; i < 2; i++)
#pragma unroll
        for (int j = 0; j < 4; j++)
            wmma::store_matrix_sync(&Cs[(wm * 32 + i * 16) * 132 + wn * 64 + j * 16],
                                    acc[i][j], 132, wmma::mem_row_major);
    __syncthreads();
    float* outp = g_ctxp[ks] + (size_t)b * Hn * Cn + nt * 128;
#pragma unroll
    for (int t = tid; t < 4096; t += 256) {
        int r = t >> 5, q = t & 31;
        *reinterpret_cast<float4*>(&outp[(size_t)r * Cn + q * 4]) =
            *reinterpret_cast<float4*>(&Cs[r * 132 + q * 4]);
    }
}

// K3r: reduce split-K partials -> g_ctx (fixed order, deterministic)
__global__ __launch_bounds__(256) void k3_reduce() {
    size_t i4 = (size_t)blockIdx.x * 256 + threadIdx.x;  // 131072 float4s
    float4 s = make_float4(0.f, 0.f, 0.f, 0.f);
#pragma unroll
    for (int k = 0; k < 8; k++) {
        float4 v = *reinterpret_cast<const float4*>(&g_ctxp[k][i4 * 4]);
        s.x += v.x; s.y += v.y; s.z += v.z; s.w += v.w;
    }
    *reinterpret_cast<float4*>(&g_ctx[i4 * 4]) = s;
}

// ---------------------------------------------------------------------------
// K4: out[b,s,c] = sum_h a[b,s,h] * ctx[b,h,c]   (per-b GEMM M=8192,N=512,K=128)
// ---------------------------------------------------------------------------
__global__ __launch_bounds__(256) void k4_out(float* __restrict__ out) {
    extern __shared__ float sm[];
    float* As = sm;                        // [128][36]  (32-wide K slice)
    float* Bs = sm + 128 * 36;             // [32][132]
    float* ivz = sm + 128 * 36 + 32 * 132; // [128]
    float* Cs = sm;                        // [128][132] overlay

    const int nt = blockIdx.x;  // c tile (0..3)
    const int mt = blockIdx.y;  // s tile (0..63)
    const int b = blockIdx.z;
    const int tid = threadIdx.x;
    const int warp = tid >> 5;
    const int wm = warp & 3, wn = warp >> 2;

    if (tid < 128) ivz[tid] = g_invz[b * Hn + tid];
    __syncthreads();

    wmma::fragment<wmma::accumulator, 16, 16, 8, float> acc[2][4];
#pragma unroll
    for (int i = 0; i < 2; i++)
#pragma unroll
        for (int j = 0; j < 4; j++) wmma::fill_fragment(acc[i][j], 0.0f);

    const float* Lb = g_logits + ((size_t)b * Sn + (size_t)mt * 128) * Hn;
    const float* Cb = g_ctx + (size_t)b * Hn * Cn + nt * 128;

    // preload K slice 0
#pragma unroll
    for (int u = 0; u < 4; u++) {
        int t = tid + 256 * u;
        int r = t >> 3, q = t & 7;
        float4 v = *reinterpret_cast<const float4*>(&Lb[(size_t)r * Hn + q * 4]);
        int hh = q * 4;
        v.x = __expf(v.x) * ivz[hh + 0];
        v.y = __expf(v.y) * ivz[hh + 1];
        v.z = __expf(v.z) * ivz[hh + 2];
        v.w = __expf(v.w) * ivz[hh + 3];
        *reinterpret_cast<float4*>(&As[r * 36 + q * 4]) = v;
    }
#pragma unroll
    for (int u = 0; u < 4; u++) {
        int t = tid + 256 * u;
        int r = t >> 5, q = t & 31;
        *reinterpret_cast<float4*>(&Bs[r * 132 + q * 4]) =
            *reinterpret_cast<const float4*>(&Cb[(size_t)r * Cn + q * 4]);
    }
    __syncthreads();

    const int NIT = Hn / 32;  // 4
    for (int it = 0; it < NIT; it++) {
        float4 pa[4], pb[4];
        if (it + 1 < NIT) {
            const int kn = (it + 1) * 32;
#pragma unroll
            for (int u = 0; u < 4; u++) {
                int t = tid + 256 * u;
                int r = t >> 3, q = t & 7;
                pa[u] = *reinterpret_cast<const float4*>(&Lb[(size_t)r * Hn + kn + q * 4]);
            }
#pragma unroll
            for (int u = 0; u < 4; u++) {
                int t = tid + 256 * u;
                int r = t >> 5, q = t & 31;
                pb[u] = *reinterpret_cast<const float4*>(&Cb[(size_t)(kn + r) * Cn + q * 4]);
            }
        }
#pragma unroll
        for (int kk = 0; kk < 32; kk += 8) {
            wmma::fragment<wmma::matrix_a, 16, 16, 8, wmma::precision::tf32, wmma::row_major> af[2];
            wmma::fragment<wmma::matrix_b, 16, 16, 8, wmma::precision::tf32, wmma::row_major> bf[4];
#pragma unroll
            for (int i = 0; i < 2; i++) {
                wmma::load_matrix_sync(af[i], &As[(wm * 32 + i * 16) * 36 + kk], 36);
#pragma unroll
                for (int e = 0; e < af[i].num_elements; e++)
                    af[i].x[e] = wmma::__float_to_tf32(af[i].x[e]);
            }
#pragma unroll
            for (int j = 0; j < 4; j++) {
                wmma::load_matrix_sync(bf[j], &Bs[kk * 132 + wn * 64 + j * 16], 132);
#pragma unroll
                for (int e = 0; e < bf[j].num_elements; e++)
                    bf[j].x[e] = wmma::__float_to_tf32(bf[j].x[e]);
            }
#pragma unroll
            for (int i = 0; i < 2; i++)
#pragma unroll
                for (int j = 0; j < 4; j++)
                    wmma::mma_sync(acc[i][j], af[i], bf[j], acc[i][j]);
        }
        __syncthreads();
        if (it + 1 < NIT) {
            const int kn = (it + 1) * 32;
#pragma unroll
            for (int u = 0; u < 4; u++) {
                int t = tid + 256 * u;
                int r = t >> 3, q = t & 7;
                float4 v = pa[u];
                int hh = kn + q * 4;            // absolute h for ivz
                v.x = __expf(v.x) * ivz[hh + 0];
                v.y = __expf(v.y) * ivz[hh + 1];
                v.z = __expf(v.z) * ivz[hh + 2];
                v.w = __expf(v.w) * ivz[hh + 3];
                *reinterpret_cast<float4*>(&As[r * 36 + q * 4]) = v;  // slice-local col
            }
#pragma unroll
            for (int u = 0; u < 4; u++) {
                int t = tid + 256 * u;
                int r = t >> 5, q = t & 31;
                *reinterpret_cast<float4*>(&Bs[r * 132 + q * 4]) = pb[u];
            }
        }
        __syncthreads();
    }

#pragma unroll
    for (int i = 0; i < 2; i++)
#pragma unroll
        for (int j = 0; j < 4; j++)
            wmma::store_matrix_sync(&Cs[(wm * 32 + i * 16) * 132 + wn * 64 + j * 16],
                                    acc[i][j], 132, wmma::mem_row_major);
    __syncthreads();
    float* Ob = out + ((size_t)b * Sn + (size_t)mt * 128) * Cn + nt * 128;
#pragma unroll
    for (int t = tid; t < 4096; t += 256) {
        int r = t >> 5, q = t & 31;
        *reinterpret_cast<float4*>(&Ob[(size_t)r * Cn + q * 4]) =
            *reinterpret_cast<float4*>(&Cs[r * 132 + q * 4]);
    }
}

// ---------------------------------------------------------------------------
extern "C" void kernel_launch(void* const* d_in, const int* in_sizes, int n_in,
                              void* d_out, int out_size) {
    const float* x = (const float*)d_in[0];
    const float* W = (const float*)d_in[1];
    const float* bias = (const float*)d_in[2];
    float* out = (float*)d_out;

    cudaFuncSetAttribute(k1_logits, cudaFuncAttributeMaxDynamicSharedMemorySize, SMEM_BYTES);
    cudaFuncSetAttribute(k3_ctx, cudaFuncAttributeMaxDynamicSharedMemorySize, SMEM_BYTES);
    cudaFuncSetAttribute(k4_out, cudaFuncAttributeMaxDynamicSharedMemorySize, SMEM_BYTES);

    k1_logits<<<512, 256, SMEM_BYTES>>>(x, W, bias);
    k2_invz<<<4, 256>>>();
    k3_ctx<<<dim3(4, 8, 8), 256, SMEM_BYTES>>>(x);
    k3_reduce<<<512, 256>>>();
    k4_out<<<dim3(4, 64, 8), 256, SMEM_BYTES>>>(out);
}

// round 14
// speedup vs baseline: 1.2355x; 1.2355x over previous
#include <cuda_runtime.h>
#include <cuda_bf16.h>
#include <cuda_pipeline.h>
#include <mma.h>

using namespace nvcuda;

#define Bn 8
#define Sn 8192
#define Cn 512
#define Hn 128

// Scratch (alloc-free rule: __device__ globals)
__device__ float g_logits[Bn * Sn * Hn];          // 32 MB
__device__ float g_ctxp[8][Bn * Hn * Cn];         // 16 MB split-K partials
__device__ float g_ctx[Bn * Hn * Cn];             // 2 MB
__device__ float g_zpart[Bn][64][Hn];             // per-K1-block partial Z
__device__ float g_invz[Bn * Hn];

// Shared layout (floats):
//   As0 [0,4608)  As1 [4608,9216)      -- 128x36 each
//   Bs0 [9216,13440) Bs1 [13440,17664) -- 32x132 each
//   ivz [17664,17792)
// Cs epilogue overlay = sm[0 .. 16896)  (128x132)
#define OFF_AS0 0
#define OFF_AS1 4608
#define OFF_BS0 9216
#define OFF_BS1 13440
#define OFF_IVZ 17664
#define SMEM_FLOATS 17792
#define SMEM_BYTES (SMEM_FLOATS * 4)

// ---------------------------------------------------------------------------
// K1: logits[b,s,h] = sum_c x[b,s,c]*W[c,h] + bias[h]
// [65536,512]@[512,128] TF32 wmma, 128x128 tile, BK=32,
// cp.async double-buffered, 1 sync/iter. Epilogue: +bias, partial Z.
// ---------------------------------------------------------------------------
__global__ __launch_bounds__(256, 2) void k1_logits(const float* __restrict__ x,
                                                    const float* __restrict__ W,
                                                    const float* __restrict__ bias) {
    extern __shared__ float sm[];
    float* Cs = sm;  // epilogue overlay
    __shared__ float red[256];

    const int m0 = blockIdx.x * 128;
    const int tid = threadIdx.x;
    const int warp = tid >> 5;
    const int wm = warp & 3, wn = warp >> 2;

    wmma::fragment<wmma::accumulator, 16, 16, 8, float> acc[2][4];
#pragma unroll
    for (int i = 0; i < 2; i++)
#pragma unroll
        for (int j = 0; j < 4; j++) wmma::fill_fragment(acc[i][j], 0.0f);

    auto stage = [&](int buf, int k0) {
        float* As = sm + (buf ? OFF_AS1 : OFF_AS0);
        float* Bs = sm + (buf ? OFF_BS1 : OFF_BS0);
#pragma unroll
        for (int u = 0; u < 4; u++) {
            int t = tid + 256 * u;
            int r = t >> 3, q = t & 7;
            __pipeline_memcpy_async(&As[r * 36 + q * 4],
                                    &x[(size_t)(m0 + r) * Cn + k0 + q * 4], 16);
        }
#pragma unroll
        for (int u = 0; u < 4; u++) {
            int t = tid + 256 * u;
            int r = t >> 5, q = t & 31;
            __pipeline_memcpy_async(&Bs[r * 132 + q * 4],
                                    &W[(size_t)(k0 + r) * Hn + q * 4], 16);
        }
    };

    stage(0, 0);
    __pipeline_commit();

    const int NIT = Cn / 32;  // 16
    for (int it = 0; it < NIT; it++) {
        __pipeline_wait_prior(0);
        __syncthreads();                       // tile `it` visible; prev iter mmas done
        if (it + 1 < NIT) {
            stage((it + 1) & 1, (it + 1) * 32);
            __pipeline_commit();
        }
        const float* As = sm + ((it & 1) ? OFF_AS1 : OFF_AS0);
        const float* Bs = sm + ((it & 1) ? OFF_BS1 : OFF_BS0);
#pragma unroll
        for (int kk = 0; kk < 32; kk += 8) {
            wmma::fragment<wmma::matrix_a, 16, 16, 8, wmma::precision::tf32, wmma::row_major> af[2];
            wmma::fragment<wmma::matrix_b, 16, 16, 8, wmma::precision::tf32, wmma::row_major> bf[4];
#pragma unroll
            for (int i = 0; i < 2; i++) {
                wmma::load_matrix_sync(af[i], &As[(wm * 32 + i * 16) * 36 + kk], 36);
#pragma unroll
                for (int e = 0; e < af[i].num_elements; e++)
                    af[i].x[e] = wmma::__float_to_tf32(af[i].x[e]);
            }
#pragma unroll
            for (int j = 0; j < 4; j++) {
                wmma::load_matrix_sync(bf[j], &Bs[kk * 132 + wn * 64 + j * 16], 132);
#pragma unroll
                for (int e = 0; e < bf[j].num_elements; e++)
                    bf[j].x[e] = wmma::__float_to_tf32(bf[j].x[e]);
            }
#pragma unroll
            for (int i = 0; i < 2; i++)
#pragma unroll
                for (int j = 0; j < 4; j++)
                    wmma::mma_sync(acc[i][j], af[i], bf[j], acc[i][j]);
        }
    }
    __syncthreads();  // all mmas done before Cs overlay reuse

#pragma unroll
    for (int i = 0; i < 2; i++)
#pragma unroll
        for (int j = 0; j < 4; j++)
            wmma::store_matrix_sync(&Cs[(wm * 32 + i * 16) * 132 + wn * 64 + j * 16],
                                    acc[i][j], 132, wmma::mem_row_major);
    __syncthreads();

#pragma unroll
    for (int t = tid; t < 4096; t += 256) {
        int r = t >> 5, q = t & 31;
        float4 v = *reinterpret_cast<float4*>(&Cs[r * 132 + q * 4]);
        float4 bb = *reinterpret_cast<const float4*>(&bias[q * 4]);
        v.x += bb.x; v.y += bb.y; v.z += bb.z; v.w += bb.w;
        *reinterpret_cast<float4*>(&g_logits[(size_t)(m0 + r) * Hn + q * 4]) = v;
    }

    const int h = tid & 127, half = tid >> 7;
    const float bh = bias[h];
    float zacc = 0.0f;
#pragma unroll
    for (int i = 0; i < 64; i++) {
        int r = 2 * i + half;
        zacc += __expf(Cs[r * 132 + h] + bh);
    }
    red[tid] = zacc;
    __syncthreads();
    if (tid < 128) {
        int bb = blockIdx.x >> 6;
        int mblk = blockIdx.x & 63;
        g_zpart[bb][mblk][tid] = red[tid] + red[tid + 128];
    }
}

// K2b: invZ = 1 / sum over 64 block partials (deterministic fixed order)
__global__ void k2_invz() {
    int idx = blockIdx.x * 256 + threadIdx.x;  // 1024 total
    int b = idx >> 7, h = idx & 127;
    float z = 0.0f;
#pragma unroll
    for (int c = 0; c < 64; c++) z += g_zpart[b][c][h];
    g_invz[idx] = 1.0f / z;
}

// ---------------------------------------------------------------------------
// K3: ctx_partial[ks][b,h,c] = sum_{s in 1024-chunk} a[b,s,h]*x[b,s,c]
// A = a^T (col-major, exp*invz during staging via LDG->reg->STS),
// B via cp.async. Double-buffered, 1 sync/iter. Split-K=8 deterministic.
// ---------------------------------------------------------------------------
__global__ __launch_bounds__(256, 2) void k3_ctx(const float* __restrict__ x) {
    extern __shared__ float sm[];
    float* ivz = sm + OFF_IVZ;
    float* Cs = sm;

    const int nt = blockIdx.x;   // c tile (0..3)
    const int ks = blockIdx.y;   // split-K chunk (0..7)
    const int b = blockIdx.z;
    const int tid = threadIdx.x;
    const int warp = tid >> 5;
    const int wm = warp & 3, wn = warp >> 2;

    if (tid < 128) ivz[tid] = g_invz[b * Hn + tid];
    __syncthreads();

    wmma::fragment<wmma::accumulator, 16, 16, 8, float> acc[2][4];
#pragma unroll
    for (int i = 0; i < 2; i++)
#pragma unroll
        for (int j = 0; j < 4; j++) wmma::fill_fragment(acc[i][j], 0.0f);

    const float* Lb = g_logits + (size_t)b * Sn * Hn;
    const float* Xb = x + (size_t)b * Sn * Cn + nt * 128;
    const int kbase = ks * 1024;
    const int r5 = tid >> 5, q5 = tid & 31;   // A/B row-col mapping (u via +8 rows)

    // stage tile 0: A synchronously (transform), B via cp.async
    {
        float* As = sm + OFF_AS0;
        float* Bs = sm + OFF_BS0;
#pragma unroll
        for (int u = 0; u < 4; u++) {
            int r = r5 + u * 8;
            float4 v = *reinterpret_cast<const float4*>(&Lb[(size_t)(kbase + r) * Hn + q5 * 4]);
            int hh = q5 * 4;
            v.x = __expf(v.x) * ivz[hh + 0];
            v.y = __expf(v.y) * ivz[hh + 1];
            v.z = __expf(v.z) * ivz[hh + 2];
            v.w = __expf(v.w) * ivz[hh + 3];
            *reinterpret_cast<float4*>(&As[r * 132 + q5 * 4]) = v;
            __pipeline_memcpy_async(&Bs[r * 132 + q5 * 4],
                                    &Xb[(size_t)(kbase + r) * Cn + q5 * 4], 16);
        }
        __pipeline_commit();
    }

    const int NIT = 32;  // 1024 / 32
    for (int it = 0; it < NIT; it++) {
        __pipeline_wait_prior(0);
        __syncthreads();
        float4 pa[4];
        const bool more = (it + 1 < NIT);
        if (more) {
            const int kn = kbase + (it + 1) * 32;
            float* Bs = sm + (((it + 1) & 1) ? OFF_BS1 : OFF_BS0);
#pragma unroll
            for (int u = 0; u < 4; u++) {
                int r = r5 + u * 8;
                pa[u] = *reinterpret_cast<const float4*>(&Lb[(size_t)(kn + r) * Hn + q5 * 4]);
                __pipeline_memcpy_async(&Bs[r * 132 + q5 * 4],
                                        &Xb[(size_t)(kn + r) * Cn + q5 * 4], 16);
            }
            __pipeline_commit();
        }
        const float* As = sm + ((it & 1) ? OFF_AS1 : OFF_AS0);
        const float* Bs = sm + ((it & 1) ? OFF_BS1 : OFF_BS0);
#pragma unroll
        for (int kk = 0; kk < 32; kk += 8) {
            wmma::fragment<wmma::matrix_a, 16, 16, 8, wmma::precision::tf32, wmma::col_major> af[2];
            wmma::fragment<wmma::matrix_b, 16, 16, 8, wmma::precision::tf32, wmma::row_major> bf[4];
#pragma unroll
            for (int i = 0; i < 2; i++) {
                wmma::load_matrix_sync(af[i], &As[kk * 132 + wm * 32 + i * 16], 132);
#pragma unroll
                for (int e = 0; e < af[i].num_elements; e++)
                    af[i].x[e] = wmma::__float_to_tf32(af[i].x[e]);
            }
#pragma unroll
            for (int j = 0; j < 4; j++) {
                wmma::load_matrix_sync(bf[j], &Bs[kk * 132 + wn * 64 + j * 16], 132);
#pragma unroll
                for (int e = 0; e < bf[j].num_elements; e++)
                    bf[j].x[e] = wmma::__float_to_tf32(bf[j].x[e]);
            }
#pragma unroll
            for (int i = 0; i < 2; i++)
#pragma unroll
                for (int j = 0; j < 4; j++)
                    wmma::mma_sync(acc[i][j], af[i], bf[j], acc[i][j]);
        }
        if (more) {  // transform + STS into next A buffer (read only after next sync)
            float* As2 = sm + (((it + 1) & 1) ? OFF_AS1 : OFF_AS0);
            int hh = q5 * 4;
#pragma unroll
            for (int u = 0; u < 4; u++) {
                int r = r5 + u * 8;
                float4 v = pa[u];
                v.x = __expf(v.x) * ivz[hh + 0];
                v.y = __expf(v.y) * ivz[hh + 1];
                v.z = __expf(v.z) * ivz[hh + 2];
                v.w = __expf(v.w) * ivz[hh + 3];
                *reinterpret_cast<float4*>(&As2[r * 132 + q5 * 4]) = v;
            }
        }
    }
    __syncthreads();

#pragma unroll
    for (int i = 0; i < 2; i++)
#pragma unroll
        for (int j = 0; j < 4; j++)
            wmma::store_matrix_sync(&Cs[(wm * 32 + i * 16) * 132 + wn * 64 + j * 16],
                                    acc[i][j], 132, wmma::mem_row_major);
    __syncthreads();
    float* outp = g_ctxp[ks] + (size_t)b * Hn * Cn + nt * 128;
#pragma unroll
    for (int t = tid; t < 4096; t += 256) {
        int r = t >> 5, q = t & 31;
        *reinterpret_cast<float4*>(&outp[(size_t)r * Cn + q * 4]) =
            *reinterpret_cast<float4*>(&Cs[r * 132 + q * 4]);
    }
}

// K3r: reduce split-K partials -> g_ctx (fixed order, deterministic)
__global__ __launch_bounds__(256) void k3_reduce() {
    size_t i4 = (size_t)blockIdx.x * 256 + threadIdx.x;  // 131072 float4s
    float4 s = make_float4(0.f, 0.f, 0.f, 0.f);
#pragma unroll
    for (int k = 0; k < 8; k++) {
        float4 v = *reinterpret_cast<const float4*>(&g_ctxp[k][i4 * 4]);
        s.x += v.x; s.y += v.y; s.z += v.z; s.w += v.w;
    }
    *reinterpret_cast<float4*>(&g_ctx[i4 * 4]) = s;
}

// ---------------------------------------------------------------------------
// K4: out[b,s,c] = sum_h a[b,s,h]*ctx[b,h,c]  (per-b GEMM M=8192,N=512,K=128)
// A via LDG+exp+STS (16 regs), B via cp.async. Double-buffered, 1 sync/iter.
// ---------------------------------------------------------------------------
__global__ __launch_bounds__(256, 2) void k4_out(float* __restrict__ out) {
    extern __shared__ float sm[];
    float* ivz = sm + OFF_IVZ;
    float* Cs = sm;

    const int nt = blockIdx.x;  // c tile (0..3)
    const int mt = blockIdx.y;  // s tile (0..63)
    const int b = blockIdx.z;
    const int tid = threadIdx.x;
    const int warp = tid >> 5;
    const int wm = warp & 3, wn = warp >> 2;

    if (tid < 128) ivz[tid] = g_invz[b * Hn + tid];
    __syncthreads();

    wmma::fragment<wmma::accumulator, 16, 16, 8, float> acc[2][4];
#pragma unroll
    for (int i = 0; i < 2; i++)
#pragma unroll
        for (int j = 0; j < 4; j++) wmma::fill_fragment(acc[i][j], 0.0f);

    const float* Lb = g_logits + ((size_t)b * Sn + (size_t)mt * 128) * Hn;
    const float* Cb = g_ctx + (size_t)b * Hn * Cn + nt * 128;
    const int r3 = tid >> 3, q3 = tid & 7;    // A mapping (u via +32 rows)
    const int r5 = tid >> 5, q5 = tid & 31;   // B mapping (u via +8 rows)

    // stage tile 0
    {
        float* As = sm + OFF_AS0;
        float* Bs = sm + OFF_BS0;
#pragma unroll
        for (int u = 0; u < 4; u++) {
            int r = r3 + u * 32;
            float4 v = *reinterpret_cast<const float4*>(&Lb[(size_t)r * Hn + q3 * 4]);
            int hh = q3 * 4;
            v.x = __expf(v.x) * ivz[hh + 0];
            v.y = __expf(v.y) * ivz[hh + 1];
            v.z = __expf(v.z) * ivz[hh + 2];
            v.w = __expf(v.w) * ivz[hh + 3];
            *reinterpret_cast<float4*>(&As[r * 36 + q3 * 4]) = v;
            int rb = r5 + u * 8;
            __pipeline_memcpy_async(&Bs[rb * 132 + q5 * 4],
                                    &Cb[(size_t)rb * Cn + q5 * 4], 16);
        }
        __pipeline_commit();
    }

    const int NIT = Hn / 32;  // 4
    for (int it = 0; it < NIT; it++) {
        __pipeline_wait_prior(0);
        __syncthreads();
        float4 pa[4];
        const bool more = (it + 1 < NIT);
        if (more) {
            const int kn = (it + 1) * 32;
            float* Bs = sm + (((it + 1) & 1) ? OFF_BS1 : OFF_BS0);
#pragma unroll
            for (int u = 0; u < 4; u++) {
                int r = r3 + u * 32;
                pa[u] = *reinterpret_cast<const float4*>(&Lb[(size_t)r * Hn + kn + q3 * 4]);
                int rb = r5 + u * 8;
                __pipeline_memcpy_async(&Bs[rb * 132 + q5 * 4],
                                        &Cb[(size_t)(kn + rb) * Cn + q5 * 4], 16);
            }
            __pipeline_commit();
        }
        const float* As = sm + ((it & 1) ? OFF_AS1 : OFF_AS0);
        const float* Bs = sm + ((it & 1) ? OFF_BS1 : OFF_BS0);
#pragma unroll
        for (int kk = 0; kk < 32; kk += 8) {
            wmma::fragment<wmma::matrix_a, 16, 16, 8, wmma::precision::tf32, wmma::row_major> af[2];
            wmma::fragment<wmma::matrix_b, 16, 16, 8, wmma::precision::tf32, wmma::row_major> bf[4];
#pragma unroll
            for (int i = 0; i < 2; i++) {
                wmma::load_matrix_sync(af[i], &As[(wm * 32 + i * 16) * 36 + kk], 36);
#pragma unroll
                for (int e = 0; e < af[i].num_elements; e++)
                    af[i].x[e] = wmma::__float_to_tf32(af[i].x[e]);
            }
#pragma unroll
            for (int j = 0; j < 4; j++) {
                wmma::load_matrix_sync(bf[j], &Bs[kk * 132 + wn * 64 + j * 16], 132);
#pragma unroll
                for (int e = 0; e < bf[j].num_elements; e++)
                    bf[j].x[e] = wmma::__float_to_tf32(bf[j].x[e]);
            }
#pragma unroll
            for (int i = 0; i < 2; i++)
#pragma unroll
                for (int j = 0; j < 4; j++)
                    wmma::mma_sync(acc[i][j], af[i], bf[j], acc[i][j]);
        }
        if (more) {
            const int kn = (it + 1) * 32;
            float* As2 = sm + (((it + 1) & 1) ? OFF_AS1 : OFF_AS0);
            int hh = kn + q3 * 4;  // absolute h for ivz
#pragma unroll
            for (int u = 0; u < 4; u++) {
                int r = r3 + u * 32;
                float4 v = pa[u];
                v.x = __expf(v.x) * ivz[hh + 0];
                v.y = __expf(v.y) * ivz[hh + 1];
                v.z = __expf(v.z) * ivz[hh + 2];
                v.w = __expf(v.w) * ivz[hh + 3];
                *reinterpret_cast<float4*>(&As2[r * 36 + q3 * 4]) = v;
            }
        }
    }
    __syncthreads();

#pragma unroll
    for (int i = 0; i < 2; i++)
#pragma unroll
        for (int j = 0; j < 4; j++)
            wmma::store_matrix_sync(&Cs[(wm * 32 + i * 16) * 132 + wn * 64 + j * 16],
                                    acc[i][j], 132, wmma::mem_row_major);
    __syncthreads();
    float* Ob = out + ((size_t)b * Sn + (size_t)mt * 128) * Cn + nt * 128;
#pragma unroll
    for (int t = tid; t < 4096; t += 256) {
        int r = t >> 5, q = t & 31;
        *reinterpret_cast<float4*>(&Ob[(size_t)r * Cn + q * 4]) =
            *reinterpret_cast<float4*>(&Cs[r * 132 + q * 4]);
    }
}

// ---------------------------------------------------------------------------
extern "C" void kernel_launch(void* const* d_in, const int* in_sizes, int n_in,
                              void* d_out, int out_size) {
    const float* x = (const float*)d_in[0];
    const float* W = (const float*)d_in[1];
    const float* bias = (const float*)d_in[2];
    float* out = (float*)d_out;

    cudaFuncSetAttribute(k1_logits, cudaFuncAttributeMaxDynamicSharedMemorySize, SMEM_BYTES);
    cudaFuncSetAttribute(k3_ctx, cudaFuncAttributeMaxDynamicSharedMemorySize, SMEM_BYTES);
    cudaFuncSetAttribute(k4_out, cudaFuncAttributeMaxDynamicSharedMemorySize, SMEM_BYTES);

    k1_logits<<<512, 256, SMEM_BYTES>>>(x, W, bias);
    k2_invz<<<4, 256>>>();
    k3_ctx<<<dim3(4, 8, 8), 256, SMEM_BYTES>>>(x);
    k3_reduce<<<512, 256>>>();
    k4_out<<<dim3(4, 64, 8), 256, SMEM_BYTES>>>(out);
}